// round 7
// baseline (speedup 1.0000x reference)
#include <cuda_runtime.h>
#include <cuda_bf16.h>
#include <cstddef>

// Soft-Viterbi (NW-style) DP, N=M=2048, 3 states (m,x,y).
//   V[i,j,m] = th[i-1,j-1,0] + lse(V[i-1,j-1,:] + A[0,:])
//   V[i,j,x] = th[i-1,j-1,1] + lse(V[i-1,j,:]   + A[1,:])
//   V[i,j,y] = th[i-1,j-1,2] + lse(V[i,j-1,:]   + A[2,:])
// Boundary: V[0,0]=[0,NEGV,NEGV]; V[0,j>0]=NEGV; V[i>0,0]=NEGV.
// Output: lse(V[N,M,:]).
//
// Single-CTA skewed systolic wavefront:
//   TT threads; thread t owns columns [t*CC+1 .. t*CC+CC] for ALL rows and
//   processes row i = s - t + 1 at step s (one row behind thread t-1).
//   Strip-edge values cross threads via a 3-slot rotating SMEM buffer:
//   step s writes slot s%3, reads slots (s-1)%3 (row i of t-1) and
//   (s-2)%3 (row i-1 of t-1). One __syncthreads per step.

#define NN 2048
#define MM 2048
#define TT 512
#define CC 4
#define NEGV (-1.0e8f)
#define STEPS (NN + TT - 1)

static_assert(TT * CC == MM, "column coverage");

// lse3 with the exp(0)=1 max-term folded out:
//   m + log(1 + e^(o-m) + e^(l-m)),  m = max, {o,l} = the other two.
__device__ __forceinline__ float lse3f(float a, float b, float c) {
    float h = fmaxf(a, b);
    float l = fminf(a, b);
    float m = fmaxf(h, c);
    float o = fminf(h, c);
    return m + logf(1.0f + (expf(o - m) + expf(l - m)));
}

__global__ __launch_bounds__(TT, 1)
void ViterbiDecoder_5506148073875_kernel(const float* __restrict__ theta,
                                         const float* __restrict__ A,
                                         float* __restrict__ out) {
    __shared__ float eM[3][TT];
    __shared__ float eX[3][TT];
    __shared__ float eY[3][TT];

    const int t = threadIdx.x;

    // Transition rows: A[0]=Am, A[1]=Ax, A[2]=Ay; column = source state (m,x,y).
    const float a00 = A[0], a01 = A[1], a02 = A[2];
    const float a10 = A[3], a11 = A[4], a12 = A[5];
    const float a20 = A[6], a21 = A[7], a22 = A[8];

    // Previous-row values for this strip (row 0: all NEGV for j >= 1).
    float pm[CC], px[CC], py[CC];
#pragma unroll
    for (int c = 0; c < CC; ++c) { pm[c] = NEGV; px[c] = NEGV; py[c] = NEGV; }

    // Pre-init all edge slots to NEGV: covers row-0 reads (V[0,j]=NEGV, j>=1).
#pragma unroll
    for (int sl = 0; sl < 3; ++sl) {
        eM[sl][t] = NEGV; eX[sl][t] = NEGV; eY[sl][t] = NEGV;
    }

    // Theta prefetch registers (12 floats = 3 aligned float4 per row-strip).
    float4 c0, c1, c2;
    if (t == 0) {  // preload row 1 for thread 0 (first active at step 0)
        const float4* tp = reinterpret_cast<const float4*>(theta);
        c0 = tp[0]; c1 = tp[1]; c2 = tp[2];
    }
    __syncthreads();

    for (int s = 0; s < STEPS; ++s) {
        const int i = s - t + 1;  // row this thread processes (1-based)
        if (i >= 1 && i <= NN) {
            // Left-neighbor state: diagonal (row i-1, col j0-1) and same-row
            // (row i, col j0-1).
            float dM, dX, dY, lM, lX, lY;
            if (t == 0) {
                // Column 0 boundary: V[0,0]=[0,NEGV,NEGV]; V[i>=1,0]=NEGV.
                dM = (i == 1) ? 0.0f : NEGV;
                dX = NEGV; dY = NEGV;
                lM = NEGV; lX = NEGV; lY = NEGV;
            } else {
                const int s1 = (s + 2) % 3;  // == (s-1) mod 3 -> row i of t-1
                const int s2 = (s + 1) % 3;  // == (s-2) mod 3 -> row i-1 of t-1
                lM = eM[s1][t - 1]; lX = eX[s1][t - 1]; lY = eY[s1][t - 1];
                dM = eM[s2][t - 1]; dX = eX[s2][t - 1]; dY = eY[s2][t - 1];
            }

            const float th[12] = {c0.x, c0.y, c0.z, c0.w,
                                  c1.x, c1.y, c1.z, c1.w,
                                  c2.x, c2.y, c2.z, c2.w};

            float nm[CC], nx[CC], ny[CC];
#pragma unroll
            for (int c = 0; c < CC; ++c) {
                const float gm = (c == 0) ? dM : pm[c - 1];  // V[i-1, j-1, :]
                const float gx = (c == 0) ? dX : px[c - 1];
                const float gy = (c == 0) ? dY : py[c - 1];
                nm[c] = th[3 * c + 0] + lse3f(gm + a00, gx + a01, gy + a02);
                nx[c] = th[3 * c + 1] + lse3f(pm[c] + a10, px[c] + a11, py[c] + a12);
                const float ym = (c == 0) ? lM : nm[c - 1];  // V[i, j-1, :]
                const float yx = (c == 0) ? lX : nx[c - 1];
                const float yy = (c == 0) ? lY : ny[c - 1];
                ny[c] = th[3 * c + 2] + lse3f(ym + a20, yx + a21, yy + a22);
            }
#pragma unroll
            for (int c = 0; c < CC; ++c) { pm[c] = nm[c]; px[c] = nx[c]; py[c] = ny[c]; }

            // Publish strip-edge (last column) for thread t+1.
            eM[s % 3][t] = nm[CC - 1];
            eX[s % 3][t] = nx[CC - 1];
            eY[s % 3][t] = ny[CC - 1];

            if (i == NN && t == TT - 1)
                out[0] = lse3f(nm[CC - 1], nx[CC - 1], ny[CC - 1]);
        }

        // Prefetch theta for next step's row (hides L2 latency under barrier
        // + next step's MUFU phase).
        const int inext = i + 1;
        if (inext >= 1 && inext <= NN) {
            const float4* tp = reinterpret_cast<const float4*>(
                theta + (size_t)(inext - 1) * (MM * 3) + (size_t)t * (CC * 3));
            c0 = tp[0]; c1 = tp[1]; c2 = tp[2];
        }
        __syncthreads();
    }
}

extern "C" void kernel_launch(void* const* d_in, const int* in_sizes, int n_in,
                              void* d_out, int out_size) {
    const float* theta = (const float*)d_in[0];
    const float* A     = (const float*)d_in[1];
    if (n_in >= 2 && in_sizes[0] == 9) {  // defensive: swap if metadata order differs
        theta = (const float*)d_in[1];
        A     = (const float*)d_in[0];
    }
    ViterbiDecoder_5506148073875_kernel<<<1, TT>>>(theta, A, (float*)d_out);
}

// round 8
// speedup vs baseline: 1.4657x; 1.4657x over previous
#include <cuda_runtime.h>
#include <cuda_bf16.h>
#include <cstddef>

// Soft-Viterbi (NW-style) DP, N=M=2048, 3 states (m,x,y).
//   V[i,j,m] = th[i-1,j-1,0] + lse(V[i-1,j-1,:] + A[0,:])
//   V[i,j,x] = th[i-1,j-1,1] + lse(V[i-1,j,:]   + A[1,:])
//   V[i,j,y] = th[i-1,j-1,2] + lse(V[i,j-1,:]   + A[2,:])
// Boundary: V[0,0]=[0,NEGV,NEGV]; V[0,j>0]=NEGV; V[i>0,0]=NEGV.
// Output: lse(V[N,M,:]).
//
// Multi-CTA pipelined systolic wavefront:
//   G CTAs, T threads each, 1 column per thread. CTA g owns columns
//   [g*T+1 .. (g+1)*T]. Inside a CTA: thread t runs one row behind thread
//   t-1; edges cross threads via a 3-slot rotating SMEM buffer, one
//   __syncthreads per step. Across CTAs: CTA g-1's last thread streams its
//   column (V[i, g*T]) to a global buffer and publishes a progress counter
//   (st.release) every 8 rows; CTA g's thread 0 spins (ld.acquire) until the
//   row it needs is available. Lag between CTAs self-adjusts (~T + 8 rows).

#define NN 2048
#define MM 2048
#define G  8
#define T  256
#define NEGV (-1.0e8f)
#define STEPS (NN + T - 1)

static_assert(G * T == MM, "column coverage");

// Cross-CTA edge buffers: g_edge[b][i] = V[i, (b+1)*T] for i in 1..NN.
__device__ float4 g_edge[G - 1][NN + 1];
__device__ int    g_prog[G - 1];   // highest published row per boundary

__device__ __forceinline__ int ld_acquire(const int* p) {
    int v;
    asm volatile("ld.global.acquire.gpu.b32 %0, [%1];" : "=r"(v) : "l"(p) : "memory");
    return v;
}
__device__ __forceinline__ void st_release(int* p, int v) {
    asm volatile("st.global.release.gpu.b32 [%0], %1;" :: "l"(p), "r"(v) : "memory");
}

// lse3 with the exp(0)=1 max-term folded out:
//   m + log(1 + e^(o-m) + e^(l-m)),  m = max, {o,l} = the other two.
// Fast-math intrinsics: pure MUFU EX2/LG2 paths.
__device__ __forceinline__ float lse3f(float a, float b, float c) {
    float h = fmaxf(a, b);
    float l = fminf(a, b);
    float m = fmaxf(h, c);
    float o = fminf(h, c);
    return m + __logf(1.0f + (__expf(o - m) + __expf(l - m)));
}

__global__ void viterbi_init_kernel() {
    if (threadIdx.x < G - 1) g_prog[threadIdx.x] = 0;
}

__global__ __launch_bounds__(T, 1)
void ViterbiDecoder_5506148073875_kernel(const float* __restrict__ theta,
                                         const float* __restrict__ A,
                                         float* __restrict__ out) {
    __shared__ float eM[3][T];
    __shared__ float eX[3][T];
    __shared__ float eY[3][T];

    const int g = blockIdx.x;
    const int t = threadIdx.x;
    const int j = g * T + t + 1;  // 1-based global column owned by this thread

    // Transition rows: A[0]=Am, A[1]=Ax, A[2]=Ay.
    const float a00 = A[0], a01 = A[1], a02 = A[2];
    const float a10 = A[3], a11 = A[4], a12 = A[5];
    const float a20 = A[6], a21 = A[7], a22 = A[8];

    // Previous-row values for this column (row 0: NEGV for all j >= 1).
    float pm = NEGV, px = NEGV, py = NEGV;

    // Saved cross-CTA edge of the previous row (V[i-1, g*T]) for thread 0 of
    // g > 0. Row 0 of any column >= 1 is NEGV.
    float sdM = NEGV, sdX = NEGV, sdY = NEGV;

    // Pre-init all edge slots to NEGV (covers row-0 / not-yet-written reads).
#pragma unroll
    for (int sl = 0; sl < 3; ++sl) {
        eM[sl][t] = NEGV; eX[sl][t] = NEGV; eY[sl][t] = NEGV;
    }

    // Theta prefetch for this thread's first active row (i = t + 1).
    float tm, tx, ty;
    {
        const float* tp = theta + (size_t)t * (MM * 3) + (size_t)(j - 1) * 3;
        tm = tp[0]; tx = tp[1]; ty = tp[2];
    }
    __syncthreads();

    for (int s = 0; s < STEPS; ++s) {
        const int i = s - t + 1;  // 1-based row this thread processes
        if (i >= 1 && i <= NN) {
            // Neighbor column j-1: diag (row i-1) and left (row i).
            float dM, dX, dY, lM, lX, lY;
            if (t == 0) {
                if (g == 0) {
                    // Column 0 boundary: V[0,0]=[0,NEGV,NEGV]; V[i>=1,0]=NEGV.
                    dM = (i == 1) ? 0.0f : NEGV;
                    dX = NEGV; dY = NEGV;
                    lM = NEGV; lX = NEGV; lY = NEGV;
                } else {
                    dM = sdM; dX = sdX; dY = sdY;
                    // Wait until CTA g-1 has published row i of its edge.
                    while (ld_acquire(&g_prog[g - 1]) < i) { }
                    float4 e = g_edge[g - 1][i];
                    lM = e.x; lX = e.y; lY = e.z;
                    sdM = lM; sdX = lX; sdY = lY;
                }
            } else {
                const int s1 = (s + 2) % 3;  // (s-1) mod 3 -> row i   of t-1
                const int s2 = (s + 1) % 3;  // (s-2) mod 3 -> row i-1 of t-1
                lM = eM[s1][t - 1]; lX = eX[s1][t - 1]; lY = eY[s1][t - 1];
                dM = eM[s2][t - 1]; dX = eX[s2][t - 1]; dY = eY[s2][t - 1];
            }

            const float nm = tm + lse3f(dM + a00, dX + a01, dY + a02);
            const float nx = tx + lse3f(pm + a10, px + a11, py + a12);
            const float ny = ty + lse3f(lM + a20, lX + a21, lY + a22);
            pm = nm; px = nx; py = ny;

            // Publish for thread t+1 (intra-CTA).
            eM[s % 3][t] = nm;
            eX[s % 3][t] = nx;
            eY[s % 3][t] = ny;

            // Publish for CTA g+1 (cross-CTA): stream every row, release the
            // progress counter every 8 rows (orders all prior edge stores).
            if (t == T - 1 && g < G - 1) {
                g_edge[g][i] = make_float4(nm, nx, ny, 0.0f);
                if ((i & 7) == 0 || i == NN) st_release(&g_prog[g], i);
            }

            if (g == G - 1 && t == T - 1 && i == NN)
                out[0] = lse3f(nm, nx, ny);
        }

        // Prefetch theta for the next step's row (hides latency under the
        // barrier + next step's MUFU phase).
        const int inext = i + 1;
        if (inext >= 1 && inext <= NN) {
            const float* tp = theta + (size_t)(inext - 1) * (MM * 3)
                                    + (size_t)(j - 1) * 3;
            tm = tp[0]; tx = tp[1]; ty = tp[2];
        }
        __syncthreads();
    }
}

extern "C" void kernel_launch(void* const* d_in, const int* in_sizes, int n_in,
                              void* d_out, int out_size) {
    const float* theta = (const float*)d_in[0];
    const float* A     = (const float*)d_in[1];
    if (n_in >= 2 && in_sizes[0] == 9) {  // defensive: swap if metadata order differs
        theta = (const float*)d_in[1];
        A     = (const float*)d_in[0];
    }
    viterbi_init_kernel<<<1, 32>>>();  // reset cross-CTA progress (per replay)
    ViterbiDecoder_5506148073875_kernel<<<G, T>>>(theta, A, (float*)d_out);
}